// round 5
// baseline (speedup 1.0000x reference)
#include <cuda_runtime.h>
#include <math.h>

// Problem constants
#define Bsz   2048
#define Fdim  128
#define Hdim  512
#define Tlen  96
#define G3H   1536   // 3*H
#define Mtile 16     // batch rows per CTA -> 128 CTAs

// Transposed weights (k-major) in device scratch. ~4 MB total, L2-resident.
__device__ __align__(16) float d_WhhT[Hdim * G3H];  // [k][n]  k<512, n<1536
__device__ __align__(16) float d_WihT[Fdim * G3H];  // [k][n]  k<128, n<1536
__device__ __align__(16) float d_FcwT[Hdim * Fdim]; // [k][f]  k<512, f<128

// ---- packed f32x2 helpers (Blackwell sm_103a) ----
__device__ __forceinline__ unsigned long long bcast2(float a) {
    unsigned long long r;
    unsigned int u = __float_as_uint(a);
    asm("mov.b64 %0, {%1, %1};" : "=l"(r) : "r"(u));
    return r;
}
__device__ __forceinline__ void fma2(unsigned long long& d, unsigned long long a, unsigned long long b) {
    asm("fma.rn.f32x2 %0, %1, %2, %0;" : "+l"(d) : "l"(a), "l"(b));
}
__device__ __forceinline__ float2 unpack2(unsigned long long v) {
    unsigned int lo, hi;
    asm("mov.b64 {%0, %1}, %2;" : "=r"(lo), "=r"(hi) : "l"(v));
    return make_float2(__uint_as_float(lo), __uint_as_float(hi));
}

// One-time weight transpose (runs every launch; ~1 MB elems, negligible)
__global__ void gru_setup_kernel(const float* __restrict__ w_ih,
                                 const float* __restrict__ w_hh,
                                 const float* __restrict__ fc_w) {
    int idx = blockIdx.x * blockDim.x + threadIdx.x;
    if (idx < Hdim * G3H) {
        int k = idx / G3H, n = idx - k * G3H;
        d_WhhT[idx] = w_hh[n * Hdim + k];
    }
    int i2 = idx - Hdim * G3H;
    if (i2 >= 0 && i2 < Fdim * G3H) {
        int k = i2 / G3H, n = i2 - k * G3H;
        d_WihT[i2] = w_ih[n * Fdim + k];
    }
    int i3 = idx - Hdim * G3H - Fdim * G3H;
    if (i3 >= 0 && i3 < Hdim * Fdim) {
        int k = i3 / Fdim, f = i3 - k * Fdim;
        d_FcwT[i3] = fc_w[f * Hdim + k];
    }
}

// Persistent GRU kernel: one CTA owns Mtile batch rows for all T steps.
__global__ __launch_bounds__(256, 1)
void gru_kernel(const float* __restrict__ hidden,
                const float* __restrict__ b_ih,
                const float* __restrict__ b_hh,
                const float* __restrict__ fc_b,
                float* __restrict__ out) {
    extern __shared__ float smem[];
    float* hbufA = smem;                          // Mtile*Hdim
    float* hbufB = smem + Mtile * Hdim;           // Mtile*Hdim
    float* xbuf  = smem + 2 * Mtile * Hdim;       // Mtile*Fdim
    float* brz   = xbuf + Mtile * Fdim;           // 2*Hdim  (b_ih+b_hh for r,z)
    float* bin   = brz + 2 * Hdim;                // Hdim    (b_ih for n)
    float* bhn   = bin + Hdim;                    // Hdim    (b_hh for n)
    float* fcb   = bhn + Hdim;                    // Fdim

    const int tid = threadIdx.x;
    const int m0  = blockIdx.x * Mtile;

    // ---- init shared state ----
    for (int i = tid; i < Mtile * Hdim; i += 256) hbufA[i] = hidden[m0 * Hdim + i];
    for (int i = tid; i < Mtile * Fdim; i += 256) xbuf[i] = 0.f;
    for (int i = tid; i < 2 * Hdim; i += 256)     brz[i] = b_ih[i] + b_hh[i];
    for (int i = tid; i < Hdim; i += 256) {
        bin[i] = b_ih[2 * Hdim + i];
        bhn[i] = b_hh[2 * Hdim + i];
    }
    for (int i = tid; i < Fdim; i += 256)         fcb[i] = fc_b[i];
    __syncthreads();

    float* hc = hbufA;   // current h
    float* hn = hbufB;   // next h

    // Phase-1 thread mapping: 4 m-groups x 64 n-groups; tile = 4m x 4n
    const int mg = tid >> 6;        // 0..3   (rows mg*4 .. mg*4+3)
    const int ng = tid & 63;        // 0..63  (cols ng*4 .. ng*4+3 within 256-chunk)
    // Phase-2 thread mapping: 8 m-groups x 32 f-groups; tile = 2m x 4f
    const int mh = tid >> 5;        // 0..7
    const int fg = tid & 31;        // 0..31

    for (int s = 0; s < Tlen; ++s) {
        // =========== Phase 1: gates + h update (2 chunks of 256 n-cols) ===========
        #pragma unroll 1
        for (int nc = 0; nc < 2; ++nc) {
            const int col = nc * 256 + ng * 4;

            unsigned long long aR[4][2], aZ[4][2], aN[4][2], aI[4][2];
            #pragma unroll
            for (int i = 0; i < 4; ++i)
                #pragma unroll
                for (int p = 0; p < 2; ++p) {
                    aR[i][p] = 0ull; aZ[i][p] = 0ull; aN[i][p] = 0ull; aI[i][p] = 0ull;
                }

            // ---- x contribution: gi = x @ w_ih^T  (K = 128) ----
            {
                const float* wrow = d_WihT + col;
                for (int k = 0; k < Fdim; k += 4) {
                    float4 av[4];
                    #pragma unroll
                    for (int i = 0; i < 4; ++i)
                        av[i] = *reinterpret_cast<const float4*>(&xbuf[(mg * 4 + i) * Fdim + k]);
                    #pragma unroll
                    for (int kk = 0; kk < 4; ++kk) {
                        ulonglong2 wr = *reinterpret_cast<const ulonglong2*>(wrow);
                        ulonglong2 wz = *reinterpret_cast<const ulonglong2*>(wrow + Hdim);
                        ulonglong2 wn = *reinterpret_cast<const ulonglong2*>(wrow + 2 * Hdim);
                        wrow += G3H;
                        #pragma unroll
                        for (int i = 0; i < 4; ++i) {
                            const float* ap = reinterpret_cast<const float*>(&av[i]);
                            unsigned long long a2 = bcast2(ap[kk]);
                            fma2(aR[i][0], a2, wr.x); fma2(aR[i][1], a2, wr.y);
                            fma2(aZ[i][0], a2, wz.x); fma2(aZ[i][1], a2, wz.y);
                            fma2(aI[i][0], a2, wn.x); fma2(aI[i][1], a2, wn.y);
                        }
                    }
                }
            }

            // ---- h contribution: gh = h @ w_hh^T  (K = 512) ----
            {
                const float* wrow = d_WhhT + col;
                for (int k = 0; k < Hdim; k += 4) {
                    float4 av[4];
                    #pragma unroll
                    for (int i = 0; i < 4; ++i)
                        av[i] = *reinterpret_cast<const float4*>(&hc[(mg * 4 + i) * Hdim + k]);
                    #pragma unroll
                    for (int kk = 0; kk < 4; ++kk) {
                        ulonglong2 wr = *reinterpret_cast<const ulonglong2*>(wrow);
                        ulonglong2 wz = *reinterpret_cast<const ulonglong2*>(wrow + Hdim);
                        ulonglong2 wn = *reinterpret_cast<const ulonglong2*>(wrow + 2 * Hdim);
                        wrow += G3H;
                        #pragma unroll
                        for (int i = 0; i < 4; ++i) {
                            const float* ap = reinterpret_cast<const float*>(&av[i]);
                            unsigned long long a2 = bcast2(ap[kk]);
                            fma2(aR[i][0], a2, wr.x); fma2(aR[i][1], a2, wr.y);
                            fma2(aZ[i][0], a2, wz.x); fma2(aZ[i][1], a2, wz.y);
                            fma2(aN[i][0], a2, wn.x); fma2(aN[i][1], a2, wn.y);
                        }
                    }
                }
            }

            // ---- gate nonlinearity + h update ----
            #pragma unroll
            for (int i = 0; i < 4; ++i) {
                const int m = mg * 4 + i;
                #pragma unroll
                for (int p = 0; p < 2; ++p) {
                    float2 Rv = unpack2(aR[i][p]);
                    float2 Zv = unpack2(aZ[i][p]);
                    float2 Nv = unpack2(aN[i][p]);
                    float2 Iv = unpack2(aI[i][p]);
                    #pragma unroll
                    for (int q = 0; q < 2; ++q) {
                        const int c = col + p * 2 + q;
                        const float rpre = (q ? Rv.y : Rv.x) + brz[c];
                        const float zpre = (q ? Zv.y : Zv.x) + brz[Hdim + c];
                        const float r = 1.f / (1.f + expf(-rpre));
                        const float z = 1.f / (1.f + expf(-zpre));
                        const float nv = tanhf((q ? Iv.y : Iv.x) + bin[c] +
                                               r * ((q ? Nv.y : Nv.x) + bhn[c]));
                        const float hp = hc[m * Hdim + c];
                        hn[m * Hdim + c] = (1.f - z) * nv + z * hp;
                    }
                }
            }
        }
        __syncthreads();

        // =========== Phase 2: x_new = h_new @ fc_w^T + fc_b; emit output ===========
        {
            const int f0 = fg * 4;
            unsigned long long acc[2][2] = {{0ull, 0ull}, {0ull, 0ull}};
            const float* wrow = d_FcwT + f0;
            for (int k = 0; k < Hdim; k += 4) {
                float4 av[2];
                #pragma unroll
                for (int i = 0; i < 2; ++i)
                    av[i] = *reinterpret_cast<const float4*>(&hn[(mh * 2 + i) * Hdim + k]);
                #pragma unroll
                for (int kk = 0; kk < 4; ++kk) {
                    ulonglong2 w = *reinterpret_cast<const ulonglong2*>(wrow);
                    wrow += Fdim;
                    #pragma unroll
                    for (int i = 0; i < 2; ++i) {
                        const float* ap = reinterpret_cast<const float*>(&av[i]);
                        unsigned long long a2 = bcast2(ap[kk]);
                        fma2(acc[i][0], a2, w.x);
                        fma2(acc[i][1], a2, w.y);
                    }
                }
            }
            const int trow = Tlen - 1 - s;   // reference reverses time at the end
            #pragma unroll
            for (int i = 0; i < 2; ++i) {
                const int m = mh * 2 + i;
                #pragma unroll
                for (int p = 0; p < 2; ++p) {
                    float2 v = unpack2(acc[i][p]);
                    const float v0 = v.x + fcb[f0 + p * 2];
                    const float v1 = v.y + fcb[f0 + p * 2 + 1];
                    xbuf[m * Fdim + f0 + p * 2]     = v0;
                    xbuf[m * Fdim + f0 + p * 2 + 1] = v1;
                    float2 ov = make_float2(v0, v1);
                    *reinterpret_cast<float2*>(
                        &out[((m0 + m) * Tlen + trow) * Fdim + f0 + p * 2]) = ov;
                }
            }
        }
        __syncthreads();

        // ping-pong h buffers
        float* tmp = hc; hc = hn; hn = tmp;
    }
}

extern "C" void kernel_launch(void* const* d_in, const int* in_sizes, int n_in,
                              void* d_out, int out_size) {
    const float* hidden = (const float*)d_in[0];
    const float* w_ih   = (const float*)d_in[1];
    const float* w_hh   = (const float*)d_in[2];
    const float* b_ih   = (const float*)d_in[3];
    const float* b_hh   = (const float*)d_in[4];
    const float* fc_w   = (const float*)d_in[5];
    const float* fc_b   = (const float*)d_in[6];
    float* out = (float*)d_out;

    const int total = Hdim * G3H + Fdim * G3H + Hdim * Fdim;
    gru_setup_kernel<<<(total + 255) / 256, 256>>>(w_ih, w_hh, fc_w);

    const int smem_bytes =
        (2 * Mtile * Hdim + Mtile * Fdim + 2 * Hdim + Hdim + Hdim + Fdim) * (int)sizeof(float);
    cudaFuncSetAttribute(gru_kernel, cudaFuncAttributeMaxDynamicSharedMemorySize, smem_bytes);
    gru_kernel<<<Bsz / Mtile, 256, smem_bytes>>>(hidden, b_ih, b_hh, fc_b, out);
}